// round 1
// baseline (speedup 1.0000x reference)
#include <cuda_runtime.h>

// Problem: x_final[r] = mean(replicates[r, :]) * (1 - 0.8^100)
// (1 - 0.8^100) = 1 - 2.037e-10 -> rounds to 1.0f in fp32.
// So: 64 row-means over a 64 x 500000 fp32 matrix. Pure HBM stream (128 MB).

#define ROWS      64
#define N_PER_ROW 500000
#define N4        (N_PER_ROW / 4)   // 125000 float4 per row (500000 % 4 == 0)
#define CPR       37                // chunks (blocks) per row -> 37*64 = 2368 blocks
#define THREADS   256

__device__ float g_partials[ROWS * CPR];

__global__ __launch_bounds__(THREADS) void row_partial_sum_kernel(
    const float4* __restrict__ in)
{
    const int row   = blockIdx.y;
    const int chunk = blockIdx.x;
    const float4* __restrict__ rp = in + (size_t)row * N4;

    // Grid-stride over this row's float4s: blocks interleave at THREADS
    // granularity -> every warp issues fully-coalesced 128B sectors.
    float s = 0.0f;
    for (int idx = chunk * THREADS + threadIdx.x; idx < N4; idx += CPR * THREADS) {
        float4 v = rp[idx];
        s += (v.x + v.y) + (v.z + v.w);
    }

    // Intra-warp tree reduce
    #pragma unroll
    for (int o = 16; o > 0; o >>= 1)
        s += __shfl_down_sync(0xffffffffu, s, o);

    __shared__ float ws[THREADS / 32];
    if ((threadIdx.x & 31) == 0) ws[threadIdx.x >> 5] = s;
    __syncthreads();

    if (threadIdx.x < THREADS / 32) {
        s = ws[threadIdx.x];
        #pragma unroll
        for (int o = (THREADS / 64); o > 0; o >>= 1)
            s += __shfl_down_sync(0xffu, s, o);
        if (threadIdx.x == 0)
            g_partials[row * CPR + chunk] = s;
    }
}

__global__ void finalize_kernel(float* __restrict__ out)
{
    const int row = threadIdx.x;
    if (row < ROWS) {
        float s = 0.0f;
        #pragma unroll
        for (int c = 0; c < CPR; c++)
            s += g_partials[row * CPR + c];
        // factor (1 - 0.8^100) == 1.0f in fp32; just divide by N.
        out[row] = s * (1.0f / (float)N_PER_ROW);
    }
}

extern "C" void kernel_launch(void* const* d_in, const int* in_sizes, int n_in,
                              void* d_out, int out_size)
{
    const float4* in = (const float4*)d_in[0];
    float* out = (float*)d_out;

    dim3 grid(CPR, ROWS, 1);
    row_partial_sum_kernel<<<grid, THREADS>>>(in);
    finalize_kernel<<<1, 64>>>(out);
}

// round 2
// speedup vs baseline: 1.1618x; 1.1618x over previous
#include <cuda_runtime.h>

// x_final[r] = mean(replicates[r, :]) * (1 - 0.8^100); the factor == 1.0f in fp32.
// => 64 row-means over a 64 x 500000 fp32 matrix. Pure HBM stream (128 MB).
//
// Single fused kernel: one wave of 1152 blocks (18 chunks x 64 rows, 256 thr),
// x4-unrolled float4 streaming loads, block reduce, last-block-per-row finalize.

#define ROWS      64
#define N_PER_ROW 500000
#define N4        (N_PER_ROW / 4)   // 125000 float4 per row
#define CPR       18                // chunks per row -> 18*64 = 1152 blocks = 1 wave @ occ 8
#define THREADS   256
#define STRIDE    (CPR * THREADS)   // 4608

__device__ float        g_partials[ROWS * CPR];
__device__ unsigned int g_count[ROWS];   // zero-initialized; reset by last block each call

__global__ __launch_bounds__(THREADS) void fused_row_mean_kernel(
    const float4* __restrict__ in, float* __restrict__ out)
{
    const int row   = blockIdx.y;
    const int chunk = blockIdx.x;
    const float4* __restrict__ rp = in + (size_t)row * N4;

    // ---- streaming partial sum, 4 independent accumulators for MLP ----
    int idx = chunk * THREADS + threadIdx.x;
    float s0 = 0.0f, s1 = 0.0f, s2 = 0.0f, s3 = 0.0f;

    while (idx + 3 * STRIDE < N4) {
        float4 a = __ldcs(rp + idx);
        float4 b = __ldcs(rp + idx + STRIDE);
        float4 c = __ldcs(rp + idx + 2 * STRIDE);
        float4 d = __ldcs(rp + idx + 3 * STRIDE);
        s0 += (a.x + a.y) + (a.z + a.w);
        s1 += (b.x + b.y) + (b.z + b.w);
        s2 += (c.x + c.y) + (c.z + c.w);
        s3 += (d.x + d.y) + (d.z + d.w);
        idx += 4 * STRIDE;
    }
    while (idx < N4) {
        float4 a = __ldcs(rp + idx);
        s0 += (a.x + a.y) + (a.z + a.w);
        idx += STRIDE;
    }
    float s = (s0 + s1) + (s2 + s3);

    // ---- block reduce ----
    #pragma unroll
    for (int o = 16; o > 0; o >>= 1)
        s += __shfl_down_sync(0xffffffffu, s, o);

    __shared__ float ws[THREADS / 32];
    if ((threadIdx.x & 31) == 0) ws[threadIdx.x >> 5] = s;
    __syncthreads();

    __shared__ bool is_last;
    if (threadIdx.x == 0) {
        float bs = 0.0f;
        #pragma unroll
        for (int w = 0; w < THREADS / 32; w++) bs += ws[w];
        g_partials[row * CPR + chunk] = bs;
        __threadfence();
        unsigned int prev = atomicAdd(&g_count[row], 1u);
        is_last = (prev == CPR - 1);
    }
    __syncthreads();

    // ---- last block for this row finalizes ----
    if (is_last && threadIdx.x == 0) {
        float tot = 0.0f;
        #pragma unroll
        for (int c = 0; c < CPR; c++)
            tot += g_partials[row * CPR + c];
        out[row] = tot * (1.0f / (float)N_PER_ROW);
        g_count[row] = 0;   // reset for next (graph-replayed) call
    }
}

extern "C" void kernel_launch(void* const* d_in, const int* in_sizes, int n_in,
                              void* d_out, int out_size)
{
    const float4* in = (const float4*)d_in[0];
    float* out = (float*)d_out;

    dim3 grid(CPR, ROWS, 1);
    fused_row_mean_kernel<<<grid, THREADS>>>(in, out);
}

// round 3
// speedup vs baseline: 1.1737x; 1.0102x over previous
#include <cuda_runtime.h>

// x_final[r] = mean(replicates[r,:]) * (1 - 0.8^100); factor == 1.0f in fp32.
// => 64 row-means over 64 x 500000 fp32 (128 MB pure HBM stream).
//
// R2: software-pipelined register double-buffer (always 4 LDG.128 in flight
// while consuming the previous 4) to break burst-synchronized warp phasing
// that left DRAM idle 33% of the time. One wave: 704 blocks @ occ 5.

#define ROWS      64
#define N_PER_ROW 500000
#define N4        125000            // float4 per row
#define CPR       11                // chunks per row -> 11*64 = 704 blocks (1 wave @ occ 5)
#define THREADS   256
#define S         (CPR * THREADS)   // 2816 float4 stride
// per-thread: 44 guaranteed loads (125000 = 44*2816 + 1096), +1 tail for base<1096
#define MAIN_ITERS 10               // prologue 4 + 10*4 = 44

__device__ float        g_partials[ROWS * CPR];
__device__ unsigned int g_count[ROWS];   // zero-init; reset by last block each call

__global__ __launch_bounds__(THREADS) void fused_row_mean_kernel(
    const float4* __restrict__ in, float* __restrict__ out)
{
    const int row   = blockIdx.y;
    const int chunk = blockIdx.x;
    const float4* __restrict__ rp = in + (size_t)row * N4;

    int idx = chunk * THREADS + threadIdx.x;
    float s0 = 0.0f, s1 = 0.0f, s2 = 0.0f, s3 = 0.0f;

    // ---- prologue: first batch in flight ----
    float4 a0 = __ldcs(rp + idx);
    float4 a1 = __ldcs(rp + idx + S);
    float4 a2 = __ldcs(rp + idx + 2 * S);
    float4 a3 = __ldcs(rp + idx + 3 * S);
    idx += 4 * S;

    // ---- pipelined main loop: issue next batch before consuming current ----
    #pragma unroll
    for (int it = 0; it < MAIN_ITERS; ++it) {
        float4 b0 = __ldcs(rp + idx);
        float4 b1 = __ldcs(rp + idx + S);
        float4 b2 = __ldcs(rp + idx + 2 * S);
        float4 b3 = __ldcs(rp + idx + 3 * S);
        s0 += (a0.x + a0.y) + (a0.z + a0.w);
        s1 += (a1.x + a1.y) + (a1.z + a1.w);
        s2 += (a2.x + a2.y) + (a2.z + a2.w);
        s3 += (a3.x + a3.y) + (a3.z + a3.w);
        a0 = b0; a1 = b1; a2 = b2; a3 = b3;
        idx += 4 * S;
    }

    // ---- epilogue: consume last batch ----
    s0 += (a0.x + a0.y) + (a0.z + a0.w);
    s1 += (a1.x + a1.y) + (a1.z + a1.w);
    s2 += (a2.x + a2.y) + (a2.z + a2.w);
    s3 += (a3.x + a3.y) + (a3.z + a3.w);

    // ---- tail: at most one extra element (base < 1096) ----
    if (idx < N4) {
        float4 v = __ldcs(rp + idx);
        s0 += (v.x + v.y) + (v.z + v.w);
    }

    float s = (s0 + s1) + (s2 + s3);

    // ---- block reduce ----
    #pragma unroll
    for (int o = 16; o > 0; o >>= 1)
        s += __shfl_down_sync(0xffffffffu, s, o);

    __shared__ float ws[THREADS / 32];
    if ((threadIdx.x & 31) == 0) ws[threadIdx.x >> 5] = s;
    __syncthreads();

    __shared__ bool is_last;
    if (threadIdx.x == 0) {
        float bs = 0.0f;
        #pragma unroll
        for (int w = 0; w < THREADS / 32; w++) bs += ws[w];
        g_partials[row * CPR + chunk] = bs;
        __threadfence();
        unsigned int prev = atomicAdd(&g_count[row], 1u);
        is_last = (prev == CPR - 1);
    }
    __syncthreads();

    // ---- last block for this row finalizes ----
    if (is_last && threadIdx.x == 0) {
        float tot = 0.0f;
        #pragma unroll
        for (int c = 0; c < CPR; c++)
            tot += g_partials[row * CPR + c];
        out[row] = tot * (1.0f / (float)N_PER_ROW);
        g_count[row] = 0;   // reset for next graph replay
    }
}

extern "C" void kernel_launch(void* const* d_in, const int* in_sizes, int n_in,
                              void* d_out, int out_size)
{
    const float4* in = (const float4*)d_in[0];
    float* out = (float*)d_out;

    dim3 grid(CPR, ROWS, 1);
    fused_row_mean_kernel<<<grid, THREADS>>>(in, out);
}